// round 1
// baseline (speedup 1.0000x reference)
#include <cuda_runtime.h>
#include <cstdint>
#include <cstddef>

#define T_LEN 8192
#define NB 32           // blocks per direction in scan
#define SCAN_SMEM (64*512*4 + 64*4 + 16*4)
#define VIT_SMEM  (T_LEN*27)

// ------------------------- device scratch -------------------------
__device__ float d_x0[(size_t)T_LEN * 1728];
__device__ float d_gx0[(size_t)T_LEN * 2048];
__device__ float d_gx1[(size_t)T_LEN * 2048];
__device__ float d_y0[(size_t)T_LEN * 1024];
__device__ float d_y1[(size_t)T_LEN * 1024];
__device__ float d_featbuf[(size_t)T_LEN * 27];
__device__ int   d_cnt[4];

__device__ __forceinline__ float sigmf(float x) {
    return 1.0f / (1.0f + expf(-x));
}

// ------------------------- conv feature kernel -------------------------
// features [T,1,7,64] -> x0 [T,1728] = concat(out1[16*12], out3[16*4*12], out5[16*4*12])
__global__ void __launch_bounds__(256) conv_kernel(
    const float* __restrict__ f,
    const float* __restrict__ w1, const float* __restrict__ b1,
    const float* __restrict__ w3, const float* __restrict__ b3,
    const float* __restrict__ w5, const float* __restrict__ b5,
    float* __restrict__ x0)
{
    __shared__ float fs[448];
    int t = blockIdx.x;
    const float* ft = f + (size_t)t * 448;
    for (int i = threadIdx.x; i < 448; i += 256) fs[i] = ft[i];
    __syncthreads();
    float* xo = x0 + (size_t)t * 1728;
    for (int o = threadIdx.x; o < 1728; o += 256) {
        float acc;
        if (o < 192) {
            int c = o / 12, p = o % 12;
            acc = b1[c];
            #pragma unroll
            for (int kh = 0; kh < 7; kh++)
                #pragma unroll
                for (int kw = 0; kw < 4; kw++)
                    acc += fs[kh * 64 + p * 4 + kw] * w1[c * 28 + kh * 4 + kw];
        } else if (o < 960) {
            int oo = o - 192;
            int c = oo / 48, r = oo % 48, oh = r / 12, p = r % 12;
            acc = b3[c];
            #pragma unroll
            for (int kh = 0; kh < 4; kh++)
                #pragma unroll
                for (int kw = 0; kw < 12; kw++)
                    acc += fs[(oh + kh) * 64 + p * 4 + kw] * w3[c * 48 + kh * 12 + kw];
        } else {
            int oo = o - 960;
            int c = oo / 48, r = oo % 48, oh = r / 12, p = r % 12;
            acc = b5[c];
            #pragma unroll
            for (int kh = 0; kh < 4; kh++)
                #pragma unroll
                for (int kw = 0; kw < 20; kw++)
                    acc += fs[(oh + kh) * 64 + p * 4 + kw] * w5[c * 80 + kh * 20 + kw];
        }
        xo[o] = acc;
    }
}

// ------------------------- GEMM: C[M,N] = A[M,K] * W[N,K]^T + b1 + b2 ----
// BM=128, BN=64, BK=16, 256 threads, thread tile 8x4. M%128==0, N%64==0, K%16==0.
#define BM 128
#define BN 64
#define BK 16
__global__ void __launch_bounds__(256) gemm_bias_kernel(
    const float* __restrict__ A, const float* __restrict__ W,
    const float* __restrict__ b1, const float* __restrict__ b2,
    float* __restrict__ C, int M, int N, int K)
{
    __shared__ float As[BK][BM];
    __shared__ float Bs[BK][BN];
    int m0 = blockIdx.y * BM;
    int n0 = blockIdx.x * BN;
    int tid = threadIdx.x;
    int ty = tid >> 4;       // 0..15 -> row group of 8
    int tx = tid & 15;       // 0..15 -> col group of 4
    float acc[8][4];
    #pragma unroll
    for (int i = 0; i < 8; i++)
        #pragma unroll
        for (int j = 0; j < 4; j++) acc[i][j] = 0.0f;

    for (int kt = 0; kt < K; kt += BK) {
        // load A tile: 128x16 floats = 512 float4
        #pragma unroll
        for (int i = 0; i < 2; i++) {
            int q = tid + i * 256;           // 0..511
            int row = q >> 2;
            int kq = (q & 3) * 4;
            float4 v = *(const float4*)&A[(size_t)(m0 + row) * K + kt + kq];
            As[kq + 0][row] = v.x; As[kq + 1][row] = v.y;
            As[kq + 2][row] = v.z; As[kq + 3][row] = v.w;
        }
        // load W tile: 64x16 = 256 float4
        {
            int row = tid >> 2;
            int kq = (tid & 3) * 4;
            float4 v = *(const float4*)&W[(size_t)(n0 + row) * K + kt + kq];
            Bs[kq + 0][row] = v.x; Bs[kq + 1][row] = v.y;
            Bs[kq + 2][row] = v.z; Bs[kq + 3][row] = v.w;
        }
        __syncthreads();
        #pragma unroll
        for (int k = 0; k < BK; k++) {
            float4 a0 = *(const float4*)&As[k][ty * 8];
            float4 a1 = *(const float4*)&As[k][ty * 8 + 4];
            float4 bb = *(const float4*)&Bs[k][tx * 4];
            float a[8] = {a0.x, a0.y, a0.z, a0.w, a1.x, a1.y, a1.z, a1.w};
            float bv[4] = {bb.x, bb.y, bb.z, bb.w};
            #pragma unroll
            for (int i = 0; i < 8; i++)
                #pragma unroll
                for (int j = 0; j < 4; j++)
                    acc[i][j] += a[i] * bv[j];
        }
        __syncthreads();
    }
    // epilogue with bias
    float bsum[4];
    #pragma unroll
    for (int j = 0; j < 4; j++) {
        int col = n0 + tx * 4 + j;
        bsum[j] = b1[col] + b2[col];
    }
    #pragma unroll
    for (int i = 0; i < 8; i++) {
        int row = m0 + ty * 8 + i;
        float4 v;
        v.x = acc[i][0] + bsum[0];
        v.y = acc[i][1] + bsum[1];
        v.z = acc[i][2] + bsum[2];
        v.w = acc[i][3] + bsum[3];
        *(float4*)&C[(size_t)row * N + n0 + tx * 4] = v;
    }
}

// ------------------------- counter reset -------------------------
__global__ void reset_kernel() {
    if (threadIdx.x < 4) d_cnt[threadIdx.x] = 0;
}

// ------------------------- persistent biLSTM scan -------------------------
// Grid: 64 blocks (block 0..31 fwd, 32..63 bwd), 256 threads.
// Block b of direction dir owns hidden units [b*16, b*16+16).
// Weights slice (64 rows x 512) resident in SMEM. h history written to y
// (cols dir*512 + ...). Cross-block sync via per-direction counter in L2.
__global__ void __launch_bounds__(256, 1) lstm_scan_kernel(
    const float* __restrict__ gxf, const float* __restrict__ gxb,
    const float* __restrict__ whhf, const float* __restrict__ whhb,
    float* __restrict__ y, int* __restrict__ cnt, int T)
{
    extern __shared__ float sm[];
    float* Wsm = sm;                 // 64*512
    float* pre = sm + 64 * 512;      // 64
    float* cst = pre + 64;           // 16

    int bx = blockIdx.x;
    int dir = bx >> 5;               // 0 fwd, 1 bwd
    int b = bx & 31;
    const float* gx = dir ? gxb : gxf;
    const float* whh = dir ? whhb : whhf;
    int* cn = cnt + dir;

    int tid = threadIdx.x;
    int lane = tid & 31;
    int w = tid >> 5;

    // load weight slice: local row lr = gate*16 + u  -> global row gate*512 + b*16 + u
    for (int idx = tid; idx < 64 * 512; idx += 256) {
        int lr = idx >> 9, col = idx & 511;
        int g = lr >> 4, u = lr & 15;
        Wsm[idx] = whh[(size_t)((g << 9) + (b << 4) + u) * 512 + col];
    }
    if (tid < 16) cst[tid] = 0.0f;
    __syncthreads();

    float* ybase = y + (dir << 9);   // column offset dir*512

    for (int s = 0; s < T; s++) {
        int t = dir ? (T - 1 - s) : s;

        // prefetch gx for this step (independent of h -> overlaps the wait)
        float gi = 0.f, gf = 0.f, gg = 0.f, go = 0.f;
        if (tid < 16) {
            const float* gp = gx + (size_t)t * 2048 + (b << 4) + tid;
            gi = gp[0]; gf = gp[512]; gg = gp[1024]; go = gp[1536];
        }

        if (s > 0) {
            if (tid == 0) {
                int target = s << 5;   // NB * s
                while (*((volatile int*)cn) < target) { }
                __threadfence();
            }
            __syncthreads();
        }

        // load h_prev into registers (lane + 32k layout)
        float hk[16];
        if (s == 0) {
            #pragma unroll
            for (int k = 0; k < 16; k++) hk[k] = 0.0f;
        } else {
            int tprev = dir ? (t + 1) : (t - 1);
            const float* hp = ybase + (size_t)tprev * 1024;
            #pragma unroll
            for (int k = 0; k < 16; k++) hk[k] = __ldcg(&hp[lane + (k << 5)]);
        }

        // each warp computes 8 gate rows
        #pragma unroll
        for (int j = 0; j < 8; j++) {
            int lr = (w << 3) + j;
            const float* wr = &Wsm[lr << 9];
            float acc = 0.0f;
            #pragma unroll
            for (int k = 0; k < 16; k++)
                acc += wr[lane + (k << 5)] * hk[k];
            acc += __shfl_xor_sync(0xffffffffu, acc, 16);
            acc += __shfl_xor_sync(0xffffffffu, acc, 8);
            acc += __shfl_xor_sync(0xffffffffu, acc, 4);
            acc += __shfl_xor_sync(0xffffffffu, acc, 2);
            acc += __shfl_xor_sync(0xffffffffu, acc, 1);
            if (lane == 0) pre[lr] = acc;
        }
        __syncthreads();

        if (tid < 16) {
            float iv = sigmf(pre[tid] + gi);
            float fv = sigmf(pre[16 + tid] + gf);
            float gv = tanhf(pre[32 + tid] + gg);
            float ov = sigmf(pre[48 + tid] + go);
            float c = fv * cst[tid] + iv * gv;
            cst[tid] = c;
            float h = ov * tanhf(c);
            ybase[(size_t)t * 1024 + (b << 4) + tid] = h;
            __threadfence();
        }
        __syncthreads();
        if (tid == 0) atomicAdd(cn, 1);
    }
}

// ------------------------- h2t projection -------------------------
// feats[t, tag] = y1[t,:] . w[tag,:] + b[tag]; 27 warps per block, block per t
__global__ void __launch_bounds__(864) h2t_kernel(
    const float* __restrict__ y1, const float* __restrict__ w,
    const float* __restrict__ b, float* __restrict__ feats)
{
    int t = blockIdx.x;
    int wid = threadIdx.x >> 5;
    int lane = threadIdx.x & 31;
    const float* yr = y1 + (size_t)t * 1024;
    const float* wr = w + (size_t)wid * 1024;
    float acc = 0.0f;
    #pragma unroll 8
    for (int k = lane; k < 1024; k += 32)
        acc += yr[k] * wr[k];
    acc += __shfl_xor_sync(0xffffffffu, acc, 16);
    acc += __shfl_xor_sync(0xffffffffu, acc, 8);
    acc += __shfl_xor_sync(0xffffffffu, acc, 4);
    acc += __shfl_xor_sync(0xffffffffu, acc, 2);
    acc += __shfl_xor_sync(0xffffffffu, acc, 1);
    if (lane == 0) feats[(size_t)t * 27 + wid] = acc + b[wid];
}

// ------------------------- Viterbi -------------------------
// Single block, 32 threads (27 active). Backpointers in SMEM (uint8).
__global__ void viterbi_kernel(
    const float* __restrict__ feats, const float* __restrict__ trans,
    float* __restrict__ out, int T)
{
    extern __shared__ unsigned char bp[];   // T*27
    __shared__ float fv[27];
    __shared__ float fvn[27];
    __shared__ float term[27];
    int tid = threadIdx.x;

    float tr[27];
    if (tid < 27) {
        #pragma unroll
        for (int p = 0; p < 27; p++) tr[p] = trans[tid * 27 + p];
        fv[tid] = (tid == 25) ? 0.0f : -10000.0f;
    }
    __syncwarp();

    float cur[8], nxt[8];
    if (tid < 27) {
        #pragma unroll
        for (int i = 0; i < 8; i++) cur[i] = feats[(size_t)i * 27 + tid];
    }
    for (int tb = 0; tb < T; tb += 8) {
        if (tid < 27) {
            #pragma unroll
            for (int i = 0; i < 8; i++) {
                int tt = tb + 8 + i;
                nxt[i] = (tt < T) ? feats[(size_t)tt * 27 + tid] : 0.0f;
            }
        }
        #pragma unroll
        for (int i = 0; i < 8; i++) {
            int t = tb + i;
            if (tid < 27) {
                float m = -1e30f; int arg = 0;
                #pragma unroll
                for (int p = 0; p < 27; p++) {
                    float s = fv[p] + tr[p];
                    if (s > m) { m = s; arg = p; }
                }
                fvn[tid] = m + cur[i];
                bp[(size_t)t * 27 + tid] = (unsigned char)arg;
            }
            __syncwarp();
            if (tid < 27) fv[tid] = fvn[tid];
            __syncwarp();
        }
        #pragma unroll
        for (int i = 0; i < 8; i++) cur[i] = nxt[i];
    }

    if (tid < 27) term[tid] = fv[tid] + trans[26 * 27 + tid];
    __syncwarp();
    if (tid == 0) {
        float m = -1e30f; int best = 0;
        #pragma unroll
        for (int p = 0; p < 27; p++)
            if (term[p] > m) { m = term[p]; best = p; }
        out[0] = m;
        int tag = best;
        out[T] = (float)tag;                 // path[T-1]
        for (int t = T - 2; t >= 0; t--) {
            tag = bp[(size_t)(t + 1) * 27 + tag];
            out[1 + t] = (float)tag;
        }
    }
}

// ------------------------- launch -------------------------
extern "C" void kernel_launch(void* const* d_in, const int* in_sizes, int n_in,
                              void* d_out, int out_size)
{
    const float* features = (const float*)d_in[0];
    const float* conv1_w = (const float*)d_in[1];
    const float* conv1_b = (const float*)d_in[2];
    const float* conv3_w = (const float*)d_in[3];
    const float* conv3_b = (const float*)d_in[4];
    const float* conv5_w = (const float*)d_in[5];
    const float* conv5_b = (const float*)d_in[6];
    const float* wih0f = (const float*)d_in[7];
    const float* whh0f = (const float*)d_in[8];
    const float* bih0f = (const float*)d_in[9];
    const float* bhh0f = (const float*)d_in[10];
    const float* wih0r = (const float*)d_in[11];
    const float* whh0r = (const float*)d_in[12];
    const float* bih0r = (const float*)d_in[13];
    const float* bhh0r = (const float*)d_in[14];
    const float* wih1f = (const float*)d_in[15];
    const float* whh1f = (const float*)d_in[16];
    const float* bih1f = (const float*)d_in[17];
    const float* bhh1f = (const float*)d_in[18];
    const float* wih1r = (const float*)d_in[19];
    const float* whh1r = (const float*)d_in[20];
    const float* bih1r = (const float*)d_in[21];
    const float* bhh1r = (const float*)d_in[22];
    const float* h2t_w = (const float*)d_in[23];
    const float* h2t_b = (const float*)d_in[24];
    const float* trans = (const float*)d_in[25];
    float* out = (float*)d_out;

    float *x0, *gx0, *gx1, *y0, *y1, *feats;
    int* cnt;
    cudaGetSymbolAddress((void**)&x0, d_x0);
    cudaGetSymbolAddress((void**)&gx0, d_gx0);
    cudaGetSymbolAddress((void**)&gx1, d_gx1);
    cudaGetSymbolAddress((void**)&y0, d_y0);
    cudaGetSymbolAddress((void**)&y1, d_y1);
    cudaGetSymbolAddress((void**)&feats, d_featbuf);
    cudaGetSymbolAddress((void**)&cnt, d_cnt);

    cudaFuncSetAttribute(lstm_scan_kernel,
                         cudaFuncAttributeMaxDynamicSharedMemorySize, SCAN_SMEM);
    cudaFuncSetAttribute(viterbi_kernel,
                         cudaFuncAttributeMaxDynamicSharedMemorySize, VIT_SMEM);

    const int T = T_LEN;

    // 1. conv features
    conv_kernel<<<T, 256>>>(features, conv1_w, conv1_b, conv3_w, conv3_b,
                            conv5_w, conv5_b, x0);

    // 2. layer0 input projections
    dim3 g0(2048 / BN, T / BM);
    gemm_bias_kernel<<<g0, 256>>>(x0, wih0f, bih0f, bhh0f, gx0, T, 2048, 1728);
    gemm_bias_kernel<<<g0, 256>>>(x0, wih0r, bih0r, bhh0r, gx1, T, 2048, 1728);

    // 3. layer0 scan
    reset_kernel<<<1, 32>>>();
    lstm_scan_kernel<<<2 * NB, 256, SCAN_SMEM>>>(gx0, gx1, whh0f, whh0r, y0, cnt, T);

    // 4. layer1 input projections
    gemm_bias_kernel<<<g0, 256>>>(y0, wih1f, bih1f, bhh1f, gx0, T, 2048, 1024);
    gemm_bias_kernel<<<g0, 256>>>(y0, wih1r, bih1r, bhh1r, gx1, T, 2048, 1024);

    // 5. layer1 scan
    lstm_scan_kernel<<<2 * NB, 256, SCAN_SMEM>>>(gx0, gx1, whh1f, whh1r, y1, cnt + 2, T);

    // 6. tag projection
    h2t_kernel<<<T, 864>>>(y1, h2t_w, h2t_b, feats);

    // 7. viterbi decode
    viterbi_kernel<<<1, 32, VIT_SMEM>>>(feats, trans, out, T);
}